// round 8
// baseline (speedup 1.0000x reference)
#include <cuda_runtime.h>
#include <cuda_bf16.h>
#include <math.h>
#include <stdint.h>

// Problem constants (fixed shapes per reference)
#define S_LEN   4096
#define D_MODEL 1024
#define NHEADS  16
#define D_K     64

// ---------------------------------------------------------------------------
// Scratch (device globals; no allocation allowed)
// ---------------------------------------------------------------------------
__device__ __nv_bfloat16 g_xh[S_LEN * D_MODEL];
__device__ __nv_bfloat16 g_xl[S_LEN * D_MODEL];
__device__ __nv_bfloat16 g_ch[S_LEN * D_MODEL];
__device__ __nv_bfloat16 g_cl[S_LEN * D_MODEL];
__device__ __nv_bfloat16 g_Qh[S_LEN * D_MODEL];
__device__ __nv_bfloat16 g_Ql[S_LEN * D_MODEL];
__device__ __nv_bfloat16 g_Kh[S_LEN * D_MODEL];
__device__ __nv_bfloat16 g_Kl[S_LEN * D_MODEL];
__device__ __nv_bfloat16 g_Vh[S_LEN * D_MODEL];
__device__ __nv_bfloat16 g_Vl[S_LEN * D_MODEL];
__device__ __nv_bfloat16 g_wqh[D_MODEL * D_MODEL];
__device__ __nv_bfloat16 g_wql[D_MODEL * D_MODEL];
__device__ __nv_bfloat16 g_wkh[D_MODEL * D_MODEL];
__device__ __nv_bfloat16 g_wkl[D_MODEL * D_MODEL];
__device__ __nv_bfloat16 g_wvh[D_MODEL * D_MODEL];
__device__ __nv_bfloat16 g_wvl[D_MODEL * D_MODEL];
__device__ __nv_bfloat16 g_woh[D_MODEL * D_MODEL];
__device__ __nv_bfloat16 g_wol[D_MODEL * D_MODEL];

// ---------------------------------------------------------------------------
// PTX helpers (base sm_80+ features only — build targets plain compute_103)
// ---------------------------------------------------------------------------
__device__ __forceinline__ uint32_t smem_u32(const void* p) {
    uint32_t a;
    asm("{ .reg .u64 t; cvta.to.shared.u64 t, %1; cvt.u32.u64 %0, t; }"
        : "=r"(a) : "l"(p));
    return a;
}

__device__ __forceinline__ void cp_async16(uint32_t smem_dst, const void* gmem_src) {
    asm volatile("cp.async.cg.shared.global [%0], [%1], 16;\n"
                 :: "r"(smem_dst), "l"(gmem_src));
}

__device__ __forceinline__ void ldsm_x4(uint32_t* r, uint32_t addr) {
    asm volatile("ldmatrix.sync.aligned.m8n8.x4.shared.b16 {%0,%1,%2,%3}, [%4];"
                 : "=r"(r[0]), "=r"(r[1]), "=r"(r[2]), "=r"(r[3]) : "r"(addr));
}

__device__ __forceinline__ void ldsm_x4_t(uint32_t* r, uint32_t addr) {
    asm volatile("ldmatrix.sync.aligned.m8n8.x4.trans.shared.b16 {%0,%1,%2,%3}, [%4];"
                 : "=r"(r[0]), "=r"(r[1]), "=r"(r[2]), "=r"(r[3]) : "r"(addr));
}

__device__ __forceinline__ void mma_16816(float* d, const uint32_t* a, const uint32_t* b) {
    asm volatile(
        "mma.sync.aligned.m16n8k16.row.col.f32.bf16.bf16.f32 "
        "{%0,%1,%2,%3}, {%4,%5,%6,%7}, {%8,%9}, {%0,%1,%2,%3};"
        : "+f"(d[0]), "+f"(d[1]), "+f"(d[2]), "+f"(d[3])
        : "r"(a[0]), "r"(a[1]), "r"(a[2]), "r"(a[3]), "r"(b[0]), "r"(b[1]));
}

__device__ __forceinline__ float fast_exp2(float x) {
    float r; asm("ex2.approx.f32 %0, %1;" : "=f"(r) : "f"(x)); return r;
}

// pack two fp32 -> bf16x2 (x in low half, y in high half)
__device__ __forceinline__ uint32_t pack_bf(float x, float y) {
    uint32_t r;
    asm("cvt.rn.bf16x2.f32 %0, %1, %2;" : "=r"(r) : "f"(y), "f"(x));
    return r;
}
__device__ __forceinline__ float bf_lo(uint32_t r) { return __uint_as_float(r << 16); }
__device__ __forceinline__ float bf_hi(uint32_t r) { return __uint_as_float(r & 0xffff0000u); }

// ---------------------------------------------------------------------------
// Split fp32 -> bf16 hi/lo  (hi = bf16(x), lo = bf16(x - float(hi)))
// ---------------------------------------------------------------------------
__device__ __forceinline__ void split_one(const float* in, __nv_bfloat16* hi,
                                          __nv_bfloat16* lo, int i)
{
    float4 v = ((const float4*)in)[i];
    uint32_t h01 = pack_bf(v.x, v.y);
    uint32_t h23 = pack_bf(v.z, v.w);
    uint32_t l01 = pack_bf(v.x - bf_lo(h01), v.y - bf_hi(h01));
    uint32_t l23 = pack_bf(v.z - bf_lo(h23), v.w - bf_hi(h23));
    ((uint32_t*)hi)[i * 2 + 0] = h01;
    ((uint32_t*)hi)[i * 2 + 1] = h23;
    ((uint32_t*)lo)[i * 2 + 0] = l01;
    ((uint32_t*)lo)[i * 2 + 1] = l23;
}

__global__ void split_bf16_kernel(const float* __restrict__ in,
                                  __nv_bfloat16* __restrict__ hi,
                                  __nv_bfloat16* __restrict__ lo, int n4)
{
    int i = blockIdx.x * blockDim.x + threadIdx.x;
    if (i >= n4) return;
    split_one(in, hi, lo, i);
}

// All 4 weight matrices in one launch; idx>>18 routes (n_w4 = 2^18).
__global__ void split_w4_kernel(
    const float* __restrict__ w0, const float* __restrict__ w1,
    const float* __restrict__ w2, const float* __restrict__ w3,
    __nv_bfloat16* __restrict__ h0, __nv_bfloat16* __restrict__ l0,
    __nv_bfloat16* __restrict__ h1, __nv_bfloat16* __restrict__ l1,
    __nv_bfloat16* __restrict__ h2, __nv_bfloat16* __restrict__ l2,
    __nv_bfloat16* __restrict__ h3, __nv_bfloat16* __restrict__ l3)
{
    int idx = blockIdx.x * blockDim.x + threadIdx.x;
    int sel = idx >> 18;
    int i   = idx & ((1 << 18) - 1);
    const float* in = sel == 0 ? w0 : sel == 1 ? w1 : sel == 2 ? w2 : w3;
    __nv_bfloat16* hi = sel == 0 ? h0 : sel == 1 ? h1 : sel == 2 ? h2 : h3;
    __nv_bfloat16* lo = sel == 0 ? l0 : sel == 1 ? l1 : sel == 2 ? l2 : l3;
    split_one(in, hi, lo, i);
}

// ---------------------------------------------------------------------------
// Tensor-core GEMM body (HMMA, bf16, fp32 acc):
//   acc = Ahi*Bhi^T + Ahi*Blo^T + Alo*Bhi^T  over K=1024, tile 128x128
// (mma.sync tensor-bound; structure unchanged from R6)
// ---------------------------------------------------------------------------
#define GK     1024
#define GBK    32
#define ROWB   80
#define TILEB  (128 * ROWB)     // 10240
#define SETB   (4 * TILEB)      // 40960 per stage
#define GSM_TOTAL (2 * SETB)    // 81920
#define NKCH   32

__device__ __forceinline__ void load_chunk4(
    const __nv_bfloat16* __restrict__ Ah, const __nv_bfloat16* __restrict__ Al,
    const __nv_bfloat16* __restrict__ Bh, const __nv_bfloat16* __restrict__ Bl,
    int bm, int bn, int k0, uint32_t dst, int tid)
{
#pragma unroll
    for (int t = 0; t < 2; t++) {
        int u = tid + t * 256;
        int r = u >> 2;
        int c = (u & 3) * 16;
        size_t ao = (size_t)(bm + r) * GK + k0;
        size_t bo = (size_t)(bn + r) * GK + k0;
        uint32_t so = (uint32_t)(r * ROWB + c);
        cp_async16(dst + so,             (const char*)(Ah + ao) + c);
        cp_async16(dst + TILEB + so,     (const char*)(Al + ao) + c);
        cp_async16(dst + 2 * TILEB + so, (const char*)(Bh + bo) + c);
        cp_async16(dst + 3 * TILEB + so, (const char*)(Bl + bo) + c);
    }
    asm volatile("cp.async.commit_group;\n" ::: "memory");
}

__device__ __forceinline__ void gemm_body(
    const __nv_bfloat16* __restrict__ A_hi, const __nv_bfloat16* __restrict__ A_lo,
    const __nv_bfloat16* __restrict__ B_hi, const __nv_bfloat16* __restrict__ B_lo,
    int bm, int bn, uint32_t sb, float acc[2][8][4])
{
    const int tid  = threadIdx.x;
    const int lane = tid & 31;
    const int w    = tid >> 5;
    const int m_off = (w & 3) * 32;
    const int n_off = (w >> 2) * 64;

#pragma unroll
    for (int mt = 0; mt < 2; mt++)
#pragma unroll
        for (int nt = 0; nt < 8; nt++)
#pragma unroll
            for (int i = 0; i < 4; i++) acc[mt][nt][i] = 0.0f;

    const uint32_t a_off = (uint32_t)((m_off + (lane & 15)) * ROWB + 16 * (lane >> 4));
    const uint32_t b_off = (uint32_t)((n_off + (lane & 7) + 8 * (lane >> 4)) * ROWB
                                      + 16 * ((lane >> 3) & 1));

    load_chunk4(A_hi, A_lo, B_hi, B_lo, bm, bn, 0,   sb,        tid);
    load_chunk4(A_hi, A_lo, B_hi, B_lo, bm, bn, GBK, sb + SETB, tid);

    for (int i = 0; i < NKCH; i++) {
        if (i + 1 < NKCH) {
            asm volatile("cp.async.wait_group 1;\n" ::: "memory");
        } else {
            asm volatile("cp.async.wait_group 0;\n" ::: "memory");
        }
        __syncthreads();

        const uint32_t base = sb + (uint32_t)(i & 1) * SETB;
#pragma unroll
        for (int ks = 0; ks < 2; ks++) {
            uint32_t ah[2][4], al[2][4];
#pragma unroll
            for (int mt = 0; mt < 2; mt++) {
                uint32_t aadr = base + a_off + (uint32_t)(mt * 16 * ROWB + ks * 32);
                ldsm_x4(ah[mt], aadr);
                ldsm_x4(al[mt], aadr + TILEB);
            }
            uint32_t b2[8][2];
#pragma unroll
            for (int np = 0; np < 4; np++) {
                uint32_t r4[4];
                ldsm_x4(r4, base + 2 * TILEB + b_off + (uint32_t)(np * 16 * ROWB + ks * 32));
                b2[2*np][0] = r4[0]; b2[2*np][1] = r4[1];
                b2[2*np+1][0] = r4[2]; b2[2*np+1][1] = r4[3];
            }
#pragma unroll
            for (int mt = 0; mt < 2; mt++)
#pragma unroll
                for (int nt = 0; nt < 8; nt++) {
                    mma_16816(acc[mt][nt], ah[mt], b2[nt]);
                    mma_16816(acc[mt][nt], al[mt], b2[nt]);
                }
#pragma unroll
            for (int np = 0; np < 4; np++) {
                uint32_t r4[4];
                ldsm_x4(r4, base + 3 * TILEB + b_off + (uint32_t)(np * 16 * ROWB + ks * 32));
                b2[2*np][0] = r4[0]; b2[2*np][1] = r4[1];
                b2[2*np+1][0] = r4[2]; b2[2*np+1][1] = r4[3];
            }
#pragma unroll
            for (int mt = 0; mt < 2; mt++)
#pragma unroll
                for (int nt = 0; nt < 8; nt++)
                    mma_16816(acc[mt][nt], ah[mt], b2[nt]);
        }
        __syncthreads();

        if (i + 2 < NKCH)
            load_chunk4(A_hi, A_lo, B_hi, B_lo, bm, bn, (i + 2) * GBK, base, tid);
    }
}

// Fused QKV: blockIdx.x in [0,24); sel = bx>>3 routes weight/output.
__global__ __launch_bounds__(256, 2) void gemm_qkv_kernel(
    const __nv_bfloat16* __restrict__ A_hi, const __nv_bfloat16* __restrict__ A_lo,
    const __nv_bfloat16* __restrict__ Wqh, const __nv_bfloat16* __restrict__ Wql,
    const __nv_bfloat16* __restrict__ Wkh, const __nv_bfloat16* __restrict__ Wkl,
    const __nv_bfloat16* __restrict__ Wvh, const __nv_bfloat16* __restrict__ Wvl,
    __nv_bfloat16* __restrict__ Qh, __nv_bfloat16* __restrict__ Ql,
    __nv_bfloat16* __restrict__ Kh, __nv_bfloat16* __restrict__ Kl,
    __nv_bfloat16* __restrict__ Vh, __nv_bfloat16* __restrict__ Vl)
{
    extern __shared__ __align__(16) char gsm[];
    const uint32_t sb = smem_u32(gsm);
    const int sel = blockIdx.x >> 3;
    const int bn  = (blockIdx.x & 7) * 128;
    const int bm  = blockIdx.y * 128;
    const __nv_bfloat16* Bh = sel == 0 ? Wqh : sel == 1 ? Wkh : Wvh;
    const __nv_bfloat16* Bl = sel == 0 ? Wql : sel == 1 ? Wkl : Wvl;
    __nv_bfloat16* Ch = sel == 0 ? Qh : sel == 1 ? Kh : Vh;
    __nv_bfloat16* Cl = sel == 0 ? Ql : sel == 1 ? Kl : Vl;

    float acc[2][8][4];
    gemm_body(A_hi, A_lo, Bh, Bl, bm, bn, sb, acc);

    const int lane = threadIdx.x & 31;
    const int w    = threadIdx.x >> 5;
    const int m_off = (w & 3) * 32;
    const int n_off = (w >> 2) * 64;
    const int g = lane >> 2;
    const int q = lane & 3;
#pragma unroll
    for (int mt = 0; mt < 2; mt++) {
#pragma unroll
        for (int nt = 0; nt < 8; nt++) {
            int row = bm + m_off + mt * 16 + g;
            int col = bn + n_off + nt * 8 + q * 2;
            uint32_t h0 = pack_bf(acc[mt][nt][0], acc[mt][nt][1]);
            uint32_t l0 = pack_bf(acc[mt][nt][0] - bf_lo(h0),
                                  acc[mt][nt][1] - bf_hi(h0));
            *(uint32_t*)(Ch + (size_t)row * D_MODEL + col) = h0;
            *(uint32_t*)(Cl + (size_t)row * D_MODEL + col) = l0;
            uint32_t h1 = pack_bf(acc[mt][nt][2], acc[mt][nt][3]);
            uint32_t l1 = pack_bf(acc[mt][nt][2] - bf_lo(h1),
                                  acc[mt][nt][3] - bf_hi(h1));
            *(uint32_t*)(Ch + (size_t)(row + 8) * D_MODEL + col) = h1;
            *(uint32_t*)(Cl + (size_t)(row + 8) * D_MODEL + col) = l1;
        }
    }
}

// Output GEMM: fp32 C
__global__ __launch_bounds__(256, 2) void gemm_out_kernel(
    const __nv_bfloat16* __restrict__ A_hi, const __nv_bfloat16* __restrict__ A_lo,
    const __nv_bfloat16* __restrict__ B_hi, const __nv_bfloat16* __restrict__ B_lo,
    float* __restrict__ Cf)
{
    extern __shared__ __align__(16) char gsm[];
    const uint32_t sb = smem_u32(gsm);
    const int bn = blockIdx.x * 128;
    const int bm = blockIdx.y * 128;

    float acc[2][8][4];
    gemm_body(A_hi, A_lo, B_hi, B_lo, bm, bn, sb, acc);

    const int lane = threadIdx.x & 31;
    const int w    = threadIdx.x >> 5;
    const int m_off = (w & 3) * 32;
    const int n_off = (w >> 2) * 64;
    const int g = lane >> 2;
    const int q = lane & 3;
#pragma unroll
    for (int mt = 0; mt < 2; mt++) {
#pragma unroll
        for (int nt = 0; nt < 8; nt++) {
            int row = bm + m_off + mt * 16 + g;
            int col = bn + n_off + nt * 8 + q * 2;
            *(float2*)(Cf + (size_t)row * D_MODEL + col) =
                make_float2(acc[mt][nt][0], acc[mt][nt][1]);
            *(float2*)(Cf + (size_t)(row + 8) * D_MODEL + col) =
                make_float2(acc[mt][nt][2], acc[mt][nt][3]);
        }
    }
}

// ---------------------------------------------------------------------------
// Tensor-core causal flash attention (FA2-style register softmax).
// CTA: 128 q-rows x one head, 8 warps x 16 rows. 32-key tiles in a 4-stage
// cp.async ring with a SINGLE __syncthreads per tile (load issued after the
// sync; 3-deep prefetch => waits never bind). Numerics identical to R6:
// scores 3-term (QhKh+QhKl+QlKh), PV 3-term (PhVh+PhVl+PlVh).
// ---------------------------------------------------------------------------
#define AQT 128
#define AKT 32
#define AROWB 144
#define AQ_BYTES   (128 * AROWB)       // 18432
#define AKV_BYTES  (32 * AROWB)        // 4608 per tile (Kh/Kl/Vh/Vl)
#define ASET_BYTES (4 * AKV_BYTES)     // 18432 per stage
#define ANSTAGE    4
#define ASM_KV0    (2 * AQ_BYTES)      // 36864
#define ASM_TOTAL  (ASM_KV0 + ANSTAGE * ASET_BYTES)   // 110592

__device__ __forceinline__ void load_kv_tile(
    const __nv_bfloat16* __restrict__ Kh, const __nv_bfloat16* __restrict__ Kl,
    const __nv_bfloat16* __restrict__ Vh, const __nv_bfloat16* __restrict__ Vl,
    int k0, int h, uint32_t base, int tid)
{
    // 4 tiles x 32 rows x 8 16B-cols = 1024 ops; 256 threads -> 1 op/tile/thread
    int r = tid >> 3, c = tid & 7;
    uint32_t so = (uint32_t)(r * AROWB + c * 16);
    size_t  go = (size_t)(k0 + r) * D_MODEL + h * D_K + c * 8;
    cp_async16(base + 0 * AKV_BYTES + so, Kh + go);
    cp_async16(base + 1 * AKV_BYTES + so, Kl + go);
    cp_async16(base + 2 * AKV_BYTES + so, Vh + go);
    cp_async16(base + 3 * AKV_BYTES + so, Vl + go);
    asm volatile("cp.async.commit_group;\n" ::: "memory");
}

__global__ __launch_bounds__(256, 2) void flash_mma_kernel(
    const __nv_bfloat16* __restrict__ Qh, const __nv_bfloat16* __restrict__ Ql,
    const __nv_bfloat16* __restrict__ Kh, const __nv_bfloat16* __restrict__ Kl,
    const __nv_bfloat16* __restrict__ Vh, const __nv_bfloat16* __restrict__ Vl,
    __nv_bfloat16* __restrict__ Ch, __nv_bfloat16* __restrict__ Cl)
{
    extern __shared__ char smem[];
    const uint32_t sb = smem_u32(smem);
    const int tid  = threadIdx.x;
    const int lane = tid & 31;
    const int wid  = tid >> 5;
    const int m_off = wid * 16;          // 8 warps x 16 rows
    const int h  = blockIdx.y;
    const int q0 = (int)(gridDim.x - 1 - blockIdx.x) * AQT;   // heavy blocks first
    const int g  = lane >> 2;
    const int qd = lane & 3;

    // Stage Q (hi at +0, lo at +AQ_BYTES): 8 x 16B per thread
#pragma unroll
    for (int t = 0; t < 8; t++) {
        const __nv_bfloat16* src = (t < 4) ? Qh : Ql;
        int v = (t & 3) * 256 + tid;        // 0..1023
        int r = v >> 3, c = v & 7;
        cp_async16(sb + (t >> 2) * AQ_BYTES + r * AROWB + c * 16,
                   src + (size_t)(q0 + r) * D_MODEL + h * D_K + c * 8);
    }
    asm volatile("cp.async.commit_group;\n" ::: "memory");

    const int ntiles = q0 / AKT + AQT / AKT;   // >= 4
    load_kv_tile(Kh, Kl, Vh, Vl, 0 * AKT, h, sb + ASM_KV0 + 0 * ASET_BYTES, tid);
    load_kv_tile(Kh, Kl, Vh, Vl, 1 * AKT, h, sb + ASM_KV0 + 1 * ASET_BYTES, tid);
    load_kv_tile(Kh, Kl, Vh, Vl, 2 * AKT, h, sb + ASM_KV0 + 2 * ASET_BYTES, tid);

    float m_i[2] = { -1e30f, -1e30f };
    float l_i[2] = { 0.f, 0.f };
    float O[8][4];
#pragma unroll
    for (int no = 0; no < 8; no++)
#pragma unroll
        for (int i = 0; i < 4; i++) O[no][i] = 0.f;

    const float C1 = 0.18033688011112042f;   // log2(e) / sqrt(64)

    // per-thread fragment offsets (tile-invariant)
    const uint32_t q_base = sb + (uint32_t)((m_off + (lane & 15)) * AROWB + 16 * (lane >> 4));
    const uint32_t k_base = (uint32_t)(((lane & 7) + 8 * (lane >> 4)) * AROWB
                                       + 16 * ((lane >> 3) & 1));
    const uint32_t v_base = (uint32_t)(((lane & 7) + 8 * ((lane >> 3) & 1)) * AROWB
                                       + 16 * (lane >> 4));

    for (int t = 0; t < ntiles; t++) {
        if (t + 3 < ntiles) {
            asm volatile("cp.async.wait_group 2;\n" ::: "memory");
        } else {
            asm volatile("cp.async.wait_group 0;\n" ::: "memory");
        }
        __syncthreads();

        // issue next load AFTER the sync (single-barrier WAR safety; 3-deep ring)
        if (t + 3 < ntiles)
            load_kv_tile(Kh, Kl, Vh, Vl, (t + 3) * AKT, h,
                         sb + ASM_KV0 + (uint32_t)((t + 3) & 3) * ASET_BYTES, tid);

        const uint32_t kvb = sb + ASM_KV0 + (uint32_t)(t & 3) * ASET_BYTES;
        const int k0 = t * AKT;

        // ---- scores S[4][4] (16 q-rows x 32 keys), 3-term split ----
        float S[4][4];
#pragma unroll
        for (int nt = 0; nt < 4; nt++)
#pragma unroll
            for (int i = 0; i < 4; i++) S[nt][i] = 0.f;

#pragma unroll
        for (int ks = 0; ks < 4; ks++) {
            uint32_t qa[4], qla[4];
            uint32_t qaddr = q_base + (uint32_t)(ks * 32);
            ldsm_x4(qa, qaddr);
            ldsm_x4(qla, qaddr + AQ_BYTES);

            uint32_t b2[4][2];
#pragma unroll
            for (int np = 0; np < 2; np++) {
                uint32_t r4[4];
                ldsm_x4(r4, kvb + k_base + (uint32_t)(np * 16 * AROWB + ks * 32));
                b2[2*np][0] = r4[0]; b2[2*np][1] = r4[1];
                b2[2*np+1][0] = r4[2]; b2[2*np+1][1] = r4[3];
            }
#pragma unroll
            for (int nt = 0; nt < 4; nt++) {
                mma_16816(S[nt], qa,  b2[nt]);
                mma_16816(S[nt], qla, b2[nt]);
            }
#pragma unroll
            for (int np = 0; np < 2; np++) {
                uint32_t r4[4];
                ldsm_x4(r4, kvb + AKV_BYTES + k_base + (uint32_t)(np * 16 * AROWB + ks * 32));
                b2[2*np][0] = r4[0]; b2[2*np][1] = r4[1];
                b2[2*np+1][0] = r4[2]; b2[2*np+1][1] = r4[3];
            }
#pragma unroll
            for (int nt = 0; nt < 4; nt++)
                mma_16816(S[nt], qa, b2[nt]);
        }

        // ---- causal mask (boundary tiles only) ----
        if (k0 + AKT > q0) {
            int qg0 = q0 + m_off + g;
#pragma unroll
            for (int nt = 0; nt < 4; nt++) {
                int kg = k0 + nt * 8 + 2 * qd;
                if (kg     > qg0)     S[nt][0] = -1e30f;
                if (kg + 1 > qg0)     S[nt][1] = -1e30f;
                if (kg     > qg0 + 8) S[nt][2] = -1e30f;
                if (kg + 1 > qg0 + 8) S[nt][3] = -1e30f;
            }
        }

        // ---- online softmax per row half (rows g and g+8) ----
#pragma unroll
        for (int hf = 0; hf < 2; hf++) {
            float mx = -1e30f;
#pragma unroll
            for (int nt = 0; nt < 4; nt++)
                mx = fmaxf(mx, fmaxf(S[nt][2*hf], S[nt][2*hf+1]));
            mx = fmaxf(mx, __shfl_xor_sync(0xffffffffu, mx, 1));
            mx = fmaxf(mx, __shfl_xor_sync(0xffffffffu, mx, 2));
            float mold = m_i[hf];
            float mnew = fmaxf(mold, mx);
            float f  = fast_exp2((mold - mnew) * C1);
            float nm = mnew * C1;
            float sum = 0.f;
#pragma unroll
            for (int nt = 0; nt < 4; nt++) {
                float p0 = fast_exp2(fmaf(S[nt][2*hf],   C1, -nm));
                float p1 = fast_exp2(fmaf(S[nt][2*hf+1], C1, -nm));
                S[nt][2*hf] = p0; S[nt][2*hf+1] = p1;
                sum += p0 + p1;
            }
            sum += __shfl_xor_sync(0xffffffffu, sum, 1);
            sum += __shfl_xor_sync(0xffffffffu, sum, 2);
            l_i[hf] = l_i[hf] * f + sum;
            m_i[hf] = mnew;
#pragma unroll
            for (int no = 0; no < 8; no++) {
                O[no][2*hf]   *= f;
                O[no][2*hf+1] *= f;
            }
        }

        // ---- P·V, 3-term split (PhVh + PhVl + PlVh) ----
#pragma unroll
        for (int j = 0; j < 2; j++) {
            uint32_t ph[4], pl[4];
            ph[0] = pack_bf(S[2*j][0],   S[2*j][1]);
            ph[1] = pack_bf(S[2*j][2],   S[2*j][3]);
            ph[2] = pack_bf(S[2*j+1][0], S[2*j+1][1]);
            ph[3] = pack_bf(S[2*j+1][2], S[2*j+1][3]);
            pl[0] = pack_bf(S[2*j][0]   - bf_lo(ph[0]), S[2*j][1]   - bf_hi(ph[0]));
            pl[1] = pack_bf(S[2*j][2]   - bf_lo(ph[1]), S[2*j][3]   - bf_hi(ph[1]));
            pl[2] = pack_bf(S[2*j+1][0] - bf_lo(ph[2]), S[2*j+1][1] - bf_hi(ph[2]));
            pl[3] = pack_bf(S[2*j+1][2] - bf_lo(ph[3]), S[2*j+1][3] - bf_hi(ph[3]));

            uint32_t v2[8][2];
#pragma unroll
            for (int np = 0; np < 4; np++) {
                uint32_t r4[4];
                ldsm_x4_t(r4, kvb + 2 * AKV_BYTES + v_base
                              + (uint32_t)(j * 16 * AROWB + np * 32));
                v2[2*np][0] = r4[0]; v2[2*np][1] = r4[1];
                v2[2*np+1][0] = r4[2]; v2[2*np+1][1] = r4[3];
            }
#pragma unroll
            for (int no = 0; no < 8; no++) {
                mma_16816(O[no], ph, v2[no]);
                mma_16816(O[no], pl, v2[no]);
            }
#pragma unroll
            for (int np = 0; np < 4; np++) {
                uint32_t r4[4];
                ldsm_x4_t(r4, kvb + 3 * AKV_BYTES + v_base
                              + (uint32_t)(j * 16 * AROWB + np * 32));
                v2[2*np][0] = r4[0]; v2[2*np][1] = r4[1];
                v2[2*np+1][0] = r4[2]; v2[2*np+1][1] = r4[3];
            }
#pragma unroll
            for (int no = 0; no < 8; no++)
                mma_16816(O[no], ph, v2[no]);
        }
    }

    // ---- epilogue: normalize + write bf16 hi/lo context ----
    {
        float inv0 = 1.f / l_i[0];
        float inv1 = 1.f / l_i[1];
        int r0 = q0 + m_off + g;
#pragma unroll
        for (int no = 0; no < 8; no++) {
            int col = h * D_K + no * 8 + 2 * qd;
            float o0 = O[no][0] * inv0, o1 = O[no][1] * inv0;
            float o2 = O[no][2] * inv1, o3 = O[no][3] * inv1;
            uint32_t h0 = pack_bf(o0, o1);
            uint32_t l0 = pack_bf(o0 - bf_lo(h0), o1 - bf_hi(h0));
            *(uint32_t*)(Ch + (size_t)r0 * D_MODEL + col) = h0;
            *(uint32_t*)(Cl + (size_t)r0 * D_MODEL + col) = l0;
            uint32_t h1 = pack_bf(o2, o3);
            uint32_t l1 = pack_bf(o2 - bf_lo(h1), o3 - bf_hi(h1));
            *(uint32_t*)(Ch + (size_t)(r0 + 8) * D_MODEL + col) = h1;
            *(uint32_t*)(Cl + (size_t)(r0 + 8) * D_MODEL + col) = l1;
        }
    }
}

// ---------------------------------------------------------------------------
// Launch
// ---------------------------------------------------------------------------
extern "C" void kernel_launch(void* const* d_in, const int* in_sizes, int n_in,
                              void* d_out, int out_size)
{
    const float* x   = (const float*)d_in[0];
    const float* W_q = (const float*)d_in[1];
    const float* W_k = (const float*)d_in[2];
    const float* W_v = (const float*)d_in[3];
    const float* W_o = (const float*)d_in[4];
    float* out = (float*)d_out;

    static __nv_bfloat16* xh = nullptr;
    static __nv_bfloat16 *xl, *ch, *cl, *qh, *ql, *kh, *kl, *vh, *vl;
    static __nv_bfloat16 *wqh, *wql, *wkh, *wkl, *wvh, *wvl, *woh, *wol;
    if (xh == nullptr) {
        cudaGetSymbolAddress((void**)&xl, g_xl);
        cudaGetSymbolAddress((void**)&ch, g_ch);
        cudaGetSymbolAddress((void**)&cl, g_cl);
        cudaGetSymbolAddress((void**)&qh, g_Qh);
        cudaGetSymbolAddress((void**)&ql, g_Ql);
        cudaGetSymbolAddress((void**)&kh, g_Kh);
        cudaGetSymbolAddress((void**)&kl, g_Kl);
        cudaGetSymbolAddress((void**)&vh, g_Vh);
        cudaGetSymbolAddress((void**)&vl, g_Vl);
        cudaGetSymbolAddress((void**)&wqh, g_wqh);
        cudaGetSymbolAddress((void**)&wql, g_wql);
        cudaGetSymbolAddress((void**)&wkh, g_wkh);
        cudaGetSymbolAddress((void**)&wkl, g_wkl);
        cudaGetSymbolAddress((void**)&wvh, g_wvh);
        cudaGetSymbolAddress((void**)&wvl, g_wvl);
        cudaGetSymbolAddress((void**)&woh, g_woh);
        cudaGetSymbolAddress((void**)&wol, g_wol);
        cudaFuncSetAttribute(flash_mma_kernel,
                             cudaFuncAttributeMaxDynamicSharedMemorySize, ASM_TOTAL);
        cudaFuncSetAttribute(gemm_qkv_kernel,
                             cudaFuncAttributeMaxDynamicSharedMemorySize, GSM_TOTAL);
        cudaFuncSetAttribute(gemm_out_kernel,
                             cudaFuncAttributeMaxDynamicSharedMemorySize, GSM_TOTAL);
        cudaGetSymbolAddress((void**)&xh, g_xh);   // last: publishes init
    }

    const int n_x4 = S_LEN * D_MODEL / 4;      // 1M float4s
    split_bf16_kernel<<<(n_x4 + 255) / 256, 256>>>(x, xh, xl, n_x4);
    split_w4_kernel<<<(4 * (1 << 18)) / 256, 256>>>(
        W_q, W_k, W_v, W_o,
        wqh, wql, wkh, wkl, wvh, wvl, woh, wol);

    dim3 qkvgrid(24, 32);
    gemm_qkv_kernel<<<qkvgrid, 256, GSM_TOTAL>>>(
        xh, xl, wqh, wql, wkh, wkl, wvh, wvl,
        qh, ql, kh, kl, vh, vl);

    dim3 agrid(S_LEN / AQT, NHEADS);          // (32, 16)
    flash_mma_kernel<<<agrid, 256, ASM_TOTAL>>>(qh, ql, kh, kl, vh, vl, ch, cl);

    dim3 ogrid(8, 32);
    gemm_out_kernel<<<ogrid, 256, GSM_TOTAL>>>(ch, cl, woh, wol, out);
}